// round 1
// baseline (speedup 1.0000x reference)
#include <cuda_runtime.h>

// Problem constants
#define BATCH   4
#define SEQ     512
#define DMODEL  512
#define MROWS   (BATCH * SEQ)       // 2048
#define NHEADS  64                  // "head" axis = d_k in this module
#define HDIM    8                   // per-head feature dim = n_head in this module

// ---------------------------------------------------------------------------
// Scratch (no cudaMalloc allowed) — 5 x 4MB fp32 buffers
// ---------------------------------------------------------------------------
__device__ float g_qn[MROWS * DMODEL];
__device__ float g_Qp[MROWS * DMODEL];
__device__ float g_Kp[MROWS * DMODEL];
__device__ float g_Vp[MROWS * DMODEL];
__device__ float g_O [MROWS * DMODEL];

// ---------------------------------------------------------------------------
// Kernel 0: LayerNorm over last dim (512), one block per row
// ---------------------------------------------------------------------------
__global__ __launch_bounds__(256) void ln_kernel(
    const float* __restrict__ x, const float* __restrict__ gamma,
    const float* __restrict__ beta, float* __restrict__ out)
{
    int row = blockIdx.x;
    const float* xr = x + (size_t)row * DMODEL;
    int tid = threadIdx.x;
    float a0 = xr[tid];
    float a1 = xr[tid + 256];

    __shared__ float red[8];
    __shared__ float red2[8];
    int warp = tid >> 5, lane = tid & 31;

    float s = a0 + a1;
    #pragma unroll
    for (int o = 16; o; o >>= 1) s += __shfl_xor_sync(0xffffffffu, s, o);
    if (lane == 0) red[warp] = s;
    __syncthreads();
    float mean = (red[0] + red[1] + red[2] + red[3] +
                  red[4] + red[5] + red[6] + red[7]) * (1.0f / 512.0f);

    float d0 = a0 - mean, d1 = a1 - mean;
    float vs = d0 * d0 + d1 * d1;
    #pragma unroll
    for (int o = 16; o; o >>= 1) vs += __shfl_xor_sync(0xffffffffu, vs, o);
    if (lane == 0) red2[warp] = vs;
    __syncthreads();
    float var = (red2[0] + red2[1] + red2[2] + red2[3] +
                 red2[4] + red2[5] + red2[6] + red2[7]) * (1.0f / 512.0f);
    float inv = rsqrtf(var + 1e-6f);

    float* orow = out + (size_t)row * DMODEL;
    orow[tid]       = d0 * inv * gamma[tid]       + beta[tid];
    orow[tid + 256] = d1 * inv * gamma[tid + 256] + beta[tid + 256];
}

// ---------------------------------------------------------------------------
// Kernel 1/3: SGEMM  C[2048,512] = A[2048,512] @ W[512,512]^T (+ bias + resid)
// Block tile 128x64, BK=16, 256 threads, 8x4 per-thread micro-tile.
// ---------------------------------------------------------------------------
__global__ __launch_bounds__(256) void sgemm_kernel(
    const float* __restrict__ A, const float* __restrict__ W,
    float* __restrict__ C,
    const float* __restrict__ bias, const float* __restrict__ resid)
{
    const int K = DMODEL;
    __shared__ float As[16][128];
    __shared__ float Bs[16][64];

    int bm = blockIdx.y * 128;
    int bn = blockIdx.x * 64;
    int tid = threadIdx.x;
    int tx = tid & 15;        // 16 column groups
    int ty = tid >> 4;        // 16 row groups

    float acc[8][4];
    #pragma unroll
    for (int i = 0; i < 8; i++)
        #pragma unroll
        for (int j = 0; j < 4; j++) acc[i][j] = 0.0f;

    for (int k0 = 0; k0 < K; k0 += 16) {
        // Load A tile 128x16 (512 float4, 2 per thread), store transposed
        #pragma unroll
        for (int i = 0; i < 2; i++) {
            int idx = tid + i * 256;
            int r = idx >> 2;
            int c = (idx & 3) << 2;
            const float4 v = *(const float4*)(A + (size_t)(bm + r) * K + k0 + c);
            As[c + 0][r] = v.x; As[c + 1][r] = v.y;
            As[c + 2][r] = v.z; As[c + 3][r] = v.w;
        }
        // Load W tile 64x16 (256 float4, 1 per thread), store transposed
        {
            int r = tid >> 2;
            int c = (tid & 3) << 2;
            const float4 v = *(const float4*)(W + (size_t)(bn + r) * K + k0 + c);
            Bs[c + 0][r] = v.x; Bs[c + 1][r] = v.y;
            Bs[c + 2][r] = v.z; Bs[c + 3][r] = v.w;
        }
        __syncthreads();

        #pragma unroll
        for (int kk = 0; kk < 16; kk++) {
            float4 a0 = *(const float4*)&As[kk][ty * 8];
            float4 a1 = *(const float4*)&As[kk][ty * 8 + 4];
            float4 b0 = *(const float4*)&Bs[kk][tx * 4];
            float af[8] = {a0.x, a0.y, a0.z, a0.w, a1.x, a1.y, a1.z, a1.w};
            float bf[4] = {b0.x, b0.y, b0.z, b0.w};
            #pragma unroll
            for (int mi = 0; mi < 8; mi++)
                #pragma unroll
                for (int ni = 0; ni < 4; ni++)
                    acc[mi][ni] = fmaf(af[mi], bf[ni], acc[mi][ni]);
        }
        __syncthreads();
    }

    int col = bn + tx * 4;
    float4 bv = make_float4(0.f, 0.f, 0.f, 0.f);
    if (bias) bv = *(const float4*)(bias + col);
    #pragma unroll
    for (int mi = 0; mi < 8; mi++) {
        int row = bm + ty * 8 + mi;
        float4 v = make_float4(acc[mi][0] + bv.x, acc[mi][1] + bv.y,
                               acc[mi][2] + bv.z, acc[mi][3] + bv.w);
        if (resid) {
            float4 r = *(const float4*)(resid + (size_t)row * DMODEL + col);
            v.x += r.x; v.y += r.y; v.z += r.z; v.w += r.w;
        }
        *(float4*)(C + (size_t)row * DMODEL + col) = v;
    }
}

// ---------------------------------------------------------------------------
// Kernel 2: attention. One block per (b, d) pair (256 blocks, 512 threads).
// K/V tiles resident in padded smem; one warp owns one q-row at a time
// (shuffle-only softmax reductions, no __syncthreads in main loop).
// scores[q,k] = dot8(Q, K) / 8 + sim[q,k]; softmax over k; O = attn @ V.
// ---------------------------------------------------------------------------
__global__ __launch_bounds__(512, 2) void attn_kernel(
    const float* __restrict__ Qp, const float* __restrict__ Kp,
    const float* __restrict__ Vp, const float* __restrict__ sim,
    float* __restrict__ attn, float* __restrict__ O)
{
    __shared__ float Ks[512][9];   // padded: stride 9 -> conflict-free
    __shared__ float Vs[512][9];

    int bd = blockIdx.x;
    int b = bd >> 6;
    int d = bd & 63;
    int tid = threadIdx.x;

    // Base: token-major [b*512 + t][c], channel c = d*8 + e
    size_t rowbase = ((size_t)b * SEQ) * DMODEL + (size_t)d * HDIM;

    {
        const float* kp = Kp + rowbase + (size_t)tid * DMODEL;
        float4 x0 = *(const float4*)kp;
        float4 x1 = *(const float4*)(kp + 4);
        Ks[tid][0] = x0.x; Ks[tid][1] = x0.y; Ks[tid][2] = x0.z; Ks[tid][3] = x0.w;
        Ks[tid][4] = x1.x; Ks[tid][5] = x1.y; Ks[tid][6] = x1.z; Ks[tid][7] = x1.w;
        const float* vp = Vp + rowbase + (size_t)tid * DMODEL;
        float4 y0 = *(const float4*)vp;
        float4 y1 = *(const float4*)(vp + 4);
        Vs[tid][0] = y0.x; Vs[tid][1] = y0.y; Vs[tid][2] = y0.z; Vs[tid][3] = y0.w;
        Vs[tid][4] = y1.x; Vs[tid][5] = y1.y; Vs[tid][6] = y1.z; Vs[tid][7] = y1.w;
    }
    __syncthreads();

    int warp = tid >> 5, lane = tid & 31;
    size_t simbase = (size_t)bd * (SEQ * SEQ);
    const float* qpb = Qp + rowbase;
    const float inv_temp = 0.125f;   // 1/sqrt(64)

    for (int qr = warp; qr < SEQ; qr += 16) {
        // Q row (8 floats, broadcast load through L1)
        float qv[8];
        const float* qrow = qpb + (size_t)qr * DMODEL;
        #pragma unroll
        for (int e = 0; e < 8; e++) qv[e] = __ldg(qrow + e);

        const float* srow = sim + simbase + (size_t)qr * SEQ;
        float s[16];
        float mx = -3.4e38f;
        #pragma unroll
        for (int i = 0; i < 16; i++) {
            int kk = lane + i * 32;
            float sv = srow[kk];
            float acc = 0.0f;
            #pragma unroll
            for (int e = 0; e < 8; e++) acc = fmaf(qv[e], Ks[kk][e], acc);
            s[i] = fmaf(acc, inv_temp, sv);
            mx = fmaxf(mx, s[i]);
        }
        #pragma unroll
        for (int o = 16; o; o >>= 1) mx = fmaxf(mx, __shfl_xor_sync(0xffffffffu, mx, o));

        float sum = 0.0f;
        float acc8[8] = {0.f, 0.f, 0.f, 0.f, 0.f, 0.f, 0.f, 0.f};
        #pragma unroll
        for (int i = 0; i < 16; i++) {
            float p = __expf(s[i] - mx);
            s[i] = p;
            sum += p;
            int kk = lane + i * 32;
            #pragma unroll
            for (int e = 0; e < 8; e++) acc8[e] = fmaf(p, Vs[kk][e], acc8[e]);
        }
        #pragma unroll
        for (int o = 16; o; o >>= 1) sum += __shfl_xor_sync(0xffffffffu, sum, o);
        float inv = 1.0f / sum;

        if (attn) {
            float* arow = attn + simbase + (size_t)qr * SEQ;
            #pragma unroll
            for (int i = 0; i < 16; i++) arow[lane + i * 32] = s[i] * inv;
        }

        #pragma unroll
        for (int e = 0; e < 8; e++) {
            #pragma unroll
            for (int o = 16; o; o >>= 1)
                acc8[e] += __shfl_xor_sync(0xffffffffu, acc8[e], o);
        }
        if (lane == 0) {
            float* orow = O + rowbase + (size_t)qr * DMODEL;
            #pragma unroll
            for (int e = 0; e < 8; e++) orow[e] = acc8[e] * inv;
        }
    }
}

// ---------------------------------------------------------------------------
// Launch
// ---------------------------------------------------------------------------
extern "C" void kernel_launch(void* const* d_in, const int* in_sizes, int n_in,
                              void* d_out, int out_size)
{
    const float* q   = (const float*)d_in[0];
    const float* k   = (const float*)d_in[1];
    const float* v   = (const float*)d_in[2];
    const float* sim = (const float*)d_in[3];
    const float* Wq  = (const float*)d_in[4];
    const float* Wk  = (const float*)d_in[5];
    const float* Wv  = (const float*)d_in[6];
    const float* Wfc = (const float*)d_in[7];
    const float* bfc = (const float*)d_in[8];
    const float* lng = (const float*)d_in[9];
    const float* lnb = (const float*)d_in[10];

    float *qn, *Qp, *Kp, *Vp, *O;
    cudaGetSymbolAddress((void**)&qn, g_qn);
    cudaGetSymbolAddress((void**)&Qp, g_Qp);
    cudaGetSymbolAddress((void**)&Kp, g_Kp);
    cudaGetSymbolAddress((void**)&Vp, g_Vp);
    cudaGetSymbolAddress((void**)&O,  g_O);

    float* outp = (float*)d_out;
    float* attnp = nullptr;
    const long long NOUT  = (long long)MROWS * DMODEL;                 // 1,048,576
    const long long NATTN = (long long)BATCH * NHEADS * SEQ * SEQ;     // 67,108,864
    if ((long long)out_size >= NOUT + NATTN) attnp = outp + NOUT;

    // 0) LayerNorm(q)
    ln_kernel<<<MROWS, 256>>>(q, lng, lnb, qn);

    // 1) Projections: Qp = qn@Wq^T, Kp = k@Wk^T, Vp = v@Wv^T
    dim3 gg(DMODEL / 64, MROWS / 128);
    sgemm_kernel<<<gg, 256>>>(qn, Wq, Qp, nullptr, nullptr);
    sgemm_kernel<<<gg, 256>>>(k,  Wk, Kp, nullptr, nullptr);
    sgemm_kernel<<<gg, 256>>>(v,  Wv, Vp, nullptr, nullptr);

    // 2) Attention (writes attn to d_out tail if present, O to scratch)
    attn_kernel<<<BATCH * NHEADS, 512>>>(Qp, Kp, Vp, sim, attnp, O);

    // 3) FC + bias + residual -> d_out head
    sgemm_kernel<<<gg, 256>>>(O, Wfc, outp, bfc, q);
}